// round 1
// baseline (speedup 1.0000x reference)
#include <cuda_runtime.h>

// out[s, :] = W_tok[x[s], :] + b_tok + W_pos[(S-1)-s, :] + b_pos
// S = 8192, D = 1024, fp32. Inputs (metadata order): x (int32, S),
// W_tok (float32, VOCAB*D), b_tok (float32, D), W_pos (float32, MAX_CTX*D),
// b_pos (float32, D).

constexpr int SEQ   = 8192;
constexpr int EMBED = 1024;
constexpr int VEC   = EMBED / 4;  // 256 float4 per row

__global__ __launch_bounds__(256)
void linear_embedding_kernel(const int* __restrict__ x,
                             const float4* __restrict__ W_tok,
                             const float4* __restrict__ b_tok,
                             const float4* __restrict__ W_pos,
                             const float4* __restrict__ b_pos,
                             float4* __restrict__ out)
{
    int s = blockIdx.x;              // row index 0..SEQ-1
    int t = threadIdx.x;             // 0..255, one float4 per thread

    int tok = __ldg(&x[s]);
    int pos = (SEQ - 1) - s;

    float4 a  = __ldg(&W_tok[(long long)tok * VEC + t]);
    float4 p  = __ldg(&W_pos[(long long)pos * VEC + t]);
    float4 bt = __ldg(&b_tok[t]);
    float4 bp = __ldg(&b_pos[t]);

    float4 r;
    r.x = a.x + bt.x + p.x + bp.x;
    r.y = a.y + bt.y + p.y + bp.y;
    r.z = a.z + bt.z + p.z + bp.z;
    r.w = a.w + bt.w + p.w + bp.w;

    out[(long long)s * VEC + t] = r;
}

extern "C" void kernel_launch(void* const* d_in, const int* in_sizes, int n_in,
                              void* d_out, int out_size)
{
    const int*    x     = (const int*)d_in[0];
    const float4* W_tok = (const float4*)d_in[1];
    const float4* b_tok = (const float4*)d_in[2];
    const float4* W_pos = (const float4*)d_in[3];
    const float4* b_pos = (const float4*)d_in[4];
    float4* out = (float4*)d_out;

    linear_embedding_kernel<<<SEQ, 256>>>(x, W_tok, b_tok, W_pos, b_pos, out);
}

// round 2
// speedup vs baseline: 1.1168x; 1.1168x over previous
#include <cuda_runtime.h>

// out[s, :] = W_tok[x[s], :] + b_tok + W_pos[(S-1)-s, :] + b_pos
// S = 8192, D = 1024, fp32.
// R2: 4 rows per CTA -> 8 independent wide loads in flight per thread
// (latency-bound fix; DRAM was at 52.9% with MLP~2).

constexpr int SEQ   = 8192;
constexpr int EMBED = 1024;
constexpr int VEC   = EMBED / 4;   // 256 float4 per row
constexpr int ROWS  = 4;           // rows per CTA

__global__ __launch_bounds__(256)
void linear_embedding_kernel(const int* __restrict__ x,
                             const float4* __restrict__ W_tok,
                             const float4* __restrict__ b_tok,
                             const float4* __restrict__ W_pos,
                             const float4* __restrict__ b_pos,
                             float4* __restrict__ out)
{
    const int t  = threadIdx.x;        // float4 column 0..255
    const int s0 = blockIdx.x * ROWS;  // first row of this CTA

    // Front-batch token loads (broadcast within warp, independent).
    int tok[ROWS];
#pragma unroll
    for (int i = 0; i < ROWS; ++i)
        tok[i] = __ldg(&x[s0 + i]);

    // Front-batch all 2*ROWS wide loads -> high MLP.
    float4 a[ROWS], p[ROWS];
#pragma unroll
    for (int i = 0; i < ROWS; ++i)
        a[i] = __ldg(&W_tok[(long long)tok[i] * VEC + t]);
#pragma unroll
    for (int i = 0; i < ROWS; ++i)
        p[i] = __ldg(&W_pos[(long long)(SEQ - 1 - (s0 + i)) * VEC + t]);

    // Biases: L1/L2 resident after first wave; pre-sum (zeros in practice,
    // and ref comparison already tolerates this ordering: rel_err == 0).
    const float4 bt = __ldg(&b_tok[t]);
    const float4 bp = __ldg(&b_pos[t]);
    float4 b;
    b.x = bt.x + bp.x;
    b.y = bt.y + bp.y;
    b.z = bt.z + bp.z;
    b.w = bt.w + bp.w;

#pragma unroll
    for (int i = 0; i < ROWS; ++i) {
        float4 r;
        r.x = (a[i].x + p[i].x) + b.x;
        r.y = (a[i].y + p[i].y) + b.y;
        r.z = (a[i].z + p[i].z) + b.z;
        r.w = (a[i].w + p[i].w) + b.w;
        out[(long long)(s0 + i) * VEC + t] = r;
    }
}

extern "C" void kernel_launch(void* const* d_in, const int* in_sizes, int n_in,
                              void* d_out, int out_size)
{
    const int*    x     = (const int*)d_in[0];
    const float4* W_tok = (const float4*)d_in[1];
    const float4* b_tok = (const float4*)d_in[2];
    const float4* W_pos = (const float4*)d_in[3];
    const float4* b_pos = (const float4*)d_in[4];
    float4* out = (float4*)d_out;

    linear_embedding_kernel<<<SEQ / ROWS, 256>>>(x, W_tok, b_tok, W_pos, b_pos, out);
}